// round 1
// baseline (speedup 1.0000x reference)
#include <cuda_runtime.h>
#include <cstdint>

// Problem constants
#define T_LEN   16384
#define NXD     128
#define NHD     512
#define STEPS   (T_LEN - NXD)   // 16256
#define G       128             // persistent CTAs (<=148 SMs, all co-resident)
#define UPC     4               // hidden units per CTA (NHD / G)
#define ROWS    16              // 4 gates * UPC
#define NTHR    256
#define SMEM_FLOATS (T_LEN + NHD + ROWS + ROWS)

// Tagged h exchange buffers: low 32 bits = float h, high 32 bits = step tag.
__device__ unsigned long long g_hbuf[2][NHD];
// Per-(step, cta) partial of Ahy @ h
__device__ float g_partials[STEPS * G];

__device__ __forceinline__ float fsigmoid(float x) {
    x = fminf(fmaxf(x, -30.f), 30.f);
    return __fdividef(1.f, 1.f + __expf(-x));
}
__device__ __forceinline__ float ftanh_fast(float x) {
    x = fminf(fmaxf(x, -15.f), 15.f);
    float e = __expf(2.f * x);
    return __fdividef(e - 1.f, e + 1.f);
}

// Zero the tag buffers each run so graph replays never see stale tags.
__global__ void rnn_clear_kernel() {
    int i = blockIdx.x * blockDim.x + threadIdx.x;
    if (i < 2 * NHD) (&g_hbuf[0][0])[i] = 0ULL;
}

__global__ __launch_bounds__(NTHR, 1) void rnn_scan_kernel(
    const float* __restrict__ x,
    const float* __restrict__ Wf, const float* __restrict__ Uf, const float* __restrict__ bf,
    const float* __restrict__ Wi, const float* __restrict__ Ui, const float* __restrict__ bi,
    const float* __restrict__ Wo, const float* __restrict__ Uo, const float* __restrict__ bo,
    const float* __restrict__ Wc, const float* __restrict__ Uc, const float* __restrict__ bc,
    const float* __restrict__ Ahy)
{
    extern __shared__ float smem[];
    float* x_s = smem;              // [T_LEN]
    float* h_s = x_s + T_LEN;       // [NHD]
    float* z_s = h_s + NHD;         // [ROWS]
    float* b_s = z_s + ROWS;        // [ROWS]

    const int tid = threadIdx.x;
    const int cta = blockIdx.x;
    const int w   = tid >> 5;
    const int l   = tid & 31;

    // Stage full x into smem (one time).
    for (int i = tid; i < T_LEN / 4; i += NTHR)
        reinterpret_cast<float4*>(x_s)[i] = reinterpret_cast<const float4*>(x)[i];

    const float* Uarr[4] = {Uf, Ui, Uo, Uc};
    const float* Warr[4] = {Wf, Wi, Wo, Wc};
    const float* barr[4] = {bf, bi, bo, bc};

    // Each warp owns 2 rows. Row r: gate = r>>2, unit = r&3 (global j = cta*UPC + unit).
    const int r0 = 2 * w,      r1 = 2 * w + 1;
    const int g0 = r0 >> 2,    u0 = r0 & 3;
    const int g1 = r1 >> 2,    u1 = r1 & 3;
    const int j0 = cta * UPC + u0;
    const int j1 = cta * UPC + u1;

    // Weights live in registers for the whole run.
    float4 uw0[4], uw1[4];
#pragma unroll
    for (int i = 0; i < 4; ++i) {
        uw0[i] = reinterpret_cast<const float4*>(Uarr[g0] + (size_t)j0 * NHD)[32 * i + l];
        uw1[i] = reinterpret_cast<const float4*>(Uarr[g1] + (size_t)j1 * NHD)[32 * i + l];
    }
    float4 ww0 = reinterpret_cast<const float4*>(Warr[g0] + (size_t)j0 * NXD)[l];
    float4 ww1 = reinterpret_cast<const float4*>(Warr[g1] + (size_t)j1 * NXD)[l];

    if (l == 0) { b_s[r0] = barr[g0][j0]; b_s[r1] = barr[g1][j1]; }

    // Threads 0..3 carry c-state for their unit in a register; also cache Ahy row.
    float cstate = 0.f;
    float ahy = 0.f;
    if (tid < UPC) ahy = Ahy[cta * UPC + tid];

    __syncthreads();

    volatile unsigned long long* hbA = (volatile unsigned long long*)g_hbuf[0];
    volatile unsigned long long* hbB = (volatile unsigned long long*)g_hbuf[1];
    const int e0 = tid, e1 = tid + NTHR;

    for (int t = 0; t < STEPS; ++t) {
        // ---- x-window part (independent of h, do before the poll) ----
        const float* xs = x_s + t + 4 * l;
        float xv0 = xs[0], xv1 = xs[1], xv2 = xs[2], xv3 = xs[3];
        float acc0 = ww0.x * xv0 + ww0.y * xv1 + ww0.z * xv2 + ww0.w * xv3;
        float acc1 = ww1.x * xv0 + ww1.y * xv1 + ww1.z * xv2 + ww1.w * xv3;

        // ---- poll the tagged h (value+validity in one 8B word; no barrier) ----
        volatile unsigned long long* hb = (t & 1) ? hbB : hbA;
        const unsigned want = (unsigned)t;
        bool d0 = false, d1 = false;
        do {
            if (!d0) {
                unsigned long long v = hb[e0];
                if ((unsigned)(v >> 32) == want) { h_s[e0] = __uint_as_float((unsigned)v); d0 = true; }
            }
            if (!d1) {
                unsigned long long v = hb[e1];
                if ((unsigned)(v >> 32) == want) { h_s[e1] = __uint_as_float((unsigned)v); d1 = true; }
            }
        } while (!(d0 && d1));
        __syncthreads();   // h_s staged

        // ---- U @ h part (weights in regs, h from smem, vectorized) ----
#pragma unroll
        for (int i = 0; i < 4; ++i) {
            float4 h4 = reinterpret_cast<float4*>(h_s)[32 * i + l];
            acc0 += uw0[i].x * h4.x + uw0[i].y * h4.y + uw0[i].z * h4.z + uw0[i].w * h4.w;
            acc1 += uw1[i].x * h4.x + uw1[i].y * h4.y + uw1[i].z * h4.z + uw1[i].w * h4.w;
        }

        // ---- warp reduce both rows ----
#pragma unroll
        for (int o = 16; o; o >>= 1) {
            acc0 += __shfl_xor_sync(0xFFFFFFFFu, acc0, o);
            acc1 += __shfl_xor_sync(0xFFFFFFFFu, acc1, o);
        }
        if (l == 0) { z_s[r0] = acc0; z_s[r1] = acc1; }
        __syncthreads();   // z_s ready

        // ---- nonlinearity + state update + publish (threads 0..3) ----
        if (tid < UPC) {
            const int u = tid;
            float zf = z_s[0  + u] + b_s[0  + u];
            float zi = z_s[4  + u] + b_s[4  + u];
            float zo = z_s[8  + u] + b_s[8  + u];
            float zc = z_s[12 + u] + b_s[12 + u];
            float f  = fsigmoid(zf);
            float in = fsigmoid(zi);
            float o  = fsigmoid(zo);
            float gg = ftanh_fast(zc);
            cstate = f * cstate + in * gg;
            float hn = o * ftanh_fast(cstate);

            unsigned long long pv =
                ((unsigned long long)(unsigned)(t + 1) << 32) | (unsigned long long)__float_as_uint(hn);
            volatile unsigned long long* dst = ((t + 1) & 1) ? hbB : hbA;
            dst[cta * UPC + u] = pv;   // single atomic 8B store: data + tag together

            float pm = ahy * hn;
            pm += __shfl_xor_sync(0xFu, pm, 1);
            pm += __shfl_xor_sync(0xFu, pm, 2);
            if (u == 0) g_partials[(size_t)t * G + cta] = pm;
        }
    }
}

// out[t] = by + sum_c partials[t][c]
__global__ void rnn_reduce_kernel(const float* __restrict__ by, float* __restrict__ out) {
    const int t = blockIdx.x;
    float v = g_partials[(size_t)t * G + threadIdx.x];
#pragma unroll
    for (int o = 16; o; o >>= 1) v += __shfl_xor_sync(0xFFFFFFFFu, v, o);
    __shared__ float s[4];
    if ((threadIdx.x & 31) == 0) s[threadIdx.x >> 5] = v;
    __syncthreads();
    if (threadIdx.x == 0) out[t] = s[0] + s[1] + s[2] + s[3] + by[0];
}

extern "C" void kernel_launch(void* const* d_in, const int* in_sizes, int n_in,
                              void* d_out, int out_size) {
    (void)in_sizes; (void)n_in; (void)out_size;
    const float* x   = (const float*)d_in[0];
    const float* Wf  = (const float*)d_in[1];
    const float* Uf  = (const float*)d_in[2];
    const float* bf  = (const float*)d_in[3];
    const float* Wi  = (const float*)d_in[4];
    const float* Ui  = (const float*)d_in[5];
    const float* bi  = (const float*)d_in[6];
    const float* Wo  = (const float*)d_in[7];
    const float* Uo  = (const float*)d_in[8];
    const float* bo  = (const float*)d_in[9];
    const float* Wc  = (const float*)d_in[10];
    const float* Uc  = (const float*)d_in[11];
    const float* bc  = (const float*)d_in[12];
    const float* Ahy = (const float*)d_in[13];
    const float* by  = (const float*)d_in[14];
    float* out = (float*)d_out;

    const int smem_bytes = SMEM_FLOATS * (int)sizeof(float);
    cudaFuncSetAttribute(rnn_scan_kernel, cudaFuncAttributeMaxDynamicSharedMemorySize, smem_bytes);

    rnn_clear_kernel<<<1, 1024>>>();
    rnn_scan_kernel<<<G, NTHR, smem_bytes>>>(x, Wf, Uf, bf, Wi, Ui, bi,
                                             Wo, Uo, bo, Wc, Uc, bc, Ahy);
    rnn_reduce_kernel<<<STEPS, G>>>(by, out);
}